// round 11
// baseline (speedup 1.0000x reference)
#include <cuda_runtime.h>
#include <math.h>
#include <float.h>

// Problem sizes (fixed by the reference)
#define Msz 16384   // B*L = 8*2048
#define Dsz 512
#define Hsz 1024
#define Csz 8192
#define LN_EPS 1e-5f

// Scratch (static device globals — the sanctioned allocation-free route)
__device__ __align__(16) float  g_xn[(size_t)Msz * Dsz];    // 32 MB LN out
__device__ __align__(16) float2 g_t2[(size_t)Msz * Hsz];    // 128 MB split t (hi,lo)
__device__ __align__(16) float2 g_cb2[(size_t)Hsz * Csz];   // 64 MB split codebook
__device__ __align__(16) float  g_csq[Csz];
__device__ __align__(16) float  g_cand_d[4 * Msz];
__device__ __align__(16) int    g_cand_i[4 * Msz];

// ---------------------------------------------------------------------------
// TF32 split: x = hi + lo + eps, hi/lo both tf32-representable.
// x - hi is exact in fp32 (Sterbenz); dropped lo*lo term ~2^-22 relative.
// ---------------------------------------------------------------------------
__device__ __forceinline__ float2 split_tf32(float f) {
    unsigned hi, lo;
    asm("cvt.rna.tf32.f32 %0, %1;" : "=r"(hi) : "f"(f));
    float hif = __uint_as_float(hi);
    float lof = f - hif;
    asm("cvt.rna.tf32.f32 %0, %1;" : "=r"(lo) : "f"(lof));
    return make_float2(hif, __uint_as_float(lo));
}

__device__ __forceinline__ void mma_tf32(float* c, const unsigned* a,
                                         unsigned b0, unsigned b1) {
    asm volatile(
        "mma.sync.aligned.m16n8k8.row.col.f32.tf32.tf32.f32 "
        "{%0,%1,%2,%3}, {%4,%5,%6,%7}, {%8,%9}, {%0,%1,%2,%3};"
        : "+f"(c[0]), "+f"(c[1]), "+f"(c[2]), "+f"(c[3])
        : "r"(a[0]), "r"(a[1]), "r"(a[2]), "r"(a[3]), "r"(b0), "r"(b1));
}

// ---------------------------------------------------------------------------
// LayerNorm: one block (128 threads) per row of 512 floats.
// Weight (== ones) vs bias (== zeros) resolved by content.
// ---------------------------------------------------------------------------
__global__ void __launch_bounds__(128) ln_kernel(const float* __restrict__ x,
                                                 const float* __restrict__ pa,
                                                 const float* __restrict__ pb) {
    const bool a_is_w = (fabsf(pa[0] - 1.0f) < 0.0625f) && (fabsf(pa[1] - 1.0f) < 0.0625f);
    const float* w = a_is_w ? pa : pb;
    const float* b = a_is_w ? pb : pa;

    const int row = blockIdx.x;
    const int t = threadIdx.x;
    const float* xr = x + (size_t)row * Dsz;
    float v0 = xr[t], v1 = xr[t + 128], v2 = xr[t + 256], v3 = xr[t + 384];
    float s  = v0 + v1 + v2 + v3;
    float ss = v0 * v0 + v1 * v1 + v2 * v2 + v3 * v3;
#pragma unroll
    for (int o = 16; o > 0; o >>= 1) {
        s  += __shfl_xor_sync(0xffffffffu, s, o);
        ss += __shfl_xor_sync(0xffffffffu, ss, o);
    }
    __shared__ float rs[4], rss[4];
    __shared__ float smean, sinv;
    const int warp = t >> 5;
    if ((t & 31) == 0) { rs[warp] = s; rss[warp] = ss; }
    __syncthreads();
    if (t == 0) {
        float S  = rs[0] + rs[1] + rs[2] + rs[3];
        float SS = rss[0] + rss[1] + rss[2] + rss[3];
        float mean = S / (float)Dsz;
        float var  = SS / (float)Dsz - mean * mean;
        smean = mean;
        sinv  = 1.0f / sqrtf(var + LN_EPS);
    }
    __syncthreads();
    const float mean = smean, inv = sinv;
    float* orow = g_xn + (size_t)row * Dsz;
    orow[t]       = (v0 - mean) * inv * w[t]       + b[t];
    orow[t + 128] = (v1 - mean) * inv * w[t + 128] + b[t + 128];
    orow[t + 256] = (v2 - mean) * inv * w[t + 256] + b[t + 256];
    orow[t + 384] = (v3 - mean) * inv * w[t + 384] + b[t + 384];
}

// ---------------------------------------------------------------------------
// c_sq[c] = sum_h codebook[h][c]^2   (coalesced column sums, fp32)
// ---------------------------------------------------------------------------
__global__ void __launch_bounds__(256) csq_kernel(const float* __restrict__ cb) {
    const int c = blockIdx.x * blockDim.x + threadIdx.x;
    float sum = 0.f;
    for (int h = 0; h < Hsz; h++) {
        float v = cb[(size_t)h * Csz + c];
        sum = fmaf(v, v, sum);
    }
    g_csq[c] = sum;
}

// ---------------------------------------------------------------------------
// Split the codebook into tf32 (hi, lo) pairs once. Memory-bound, ~20us.
// ---------------------------------------------------------------------------
__global__ void __launch_bounds__(256) cb2_kernel(const float* __restrict__ cb) {
    const size_t i = (size_t)blockIdx.x * 256 + threadIdx.x;
    g_cb2[i] = split_tf32(cb[i]);
}

// ---------------------------------------------------------------------------
// GEMM1 (NT): t[M,H] = g_xn[M,D] * W[H,D]^T, fp32 FFMA.
// Epilogue writes SPLIT tf32 pairs into g_t2.
// ---------------------------------------------------------------------------
__global__ void __launch_bounds__(256) gemm1_kernel(const float* __restrict__ W) {
    const int m0 = blockIdx.y * 128;
    const int n0 = blockIdx.x * 128;
    __shared__ __align__(16) float As[16][132];
    __shared__ __align__(16) float Bs[16][132];
    const int tid = threadIdx.x;
    const int tx = tid & 15;
    const int ty = tid >> 4;
    const int lrow = tid >> 2;          // 0..63
    const int lk = (tid & 3) << 2;      // 0,4,8,12

    float acc[8][8];
#pragma unroll
    for (int i = 0; i < 8; i++)
#pragma unroll
        for (int j = 0; j < 8; j++) acc[i][j] = 0.f;

    const float* Ap = g_xn + (size_t)(m0 + lrow) * Dsz + lk;
    const float* Bp = W + (size_t)(n0 + lrow) * Dsz + lk;

    for (int k0 = 0; k0 < Dsz; k0 += 16) {
        float4 a0 = *(const float4*)(Ap + k0);
        float4 a1 = *(const float4*)(Ap + k0 + (size_t)64 * Dsz);
        float4 b0 = *(const float4*)(Bp + k0);
        float4 b1 = *(const float4*)(Bp + k0 + (size_t)64 * Dsz);
        __syncthreads();
        As[lk + 0][lrow] = a0.x; As[lk + 1][lrow] = a0.y;
        As[lk + 2][lrow] = a0.z; As[lk + 3][lrow] = a0.w;
        As[lk + 0][lrow + 64] = a1.x; As[lk + 1][lrow + 64] = a1.y;
        As[lk + 2][lrow + 64] = a1.z; As[lk + 3][lrow + 64] = a1.w;
        Bs[lk + 0][lrow] = b0.x; Bs[lk + 1][lrow] = b0.y;
        Bs[lk + 2][lrow] = b0.z; Bs[lk + 3][lrow] = b0.w;
        Bs[lk + 0][lrow + 64] = b1.x; Bs[lk + 1][lrow + 64] = b1.y;
        Bs[lk + 2][lrow + 64] = b1.z; Bs[lk + 3][lrow + 64] = b1.w;
        __syncthreads();
#pragma unroll
        for (int kk = 0; kk < 16; kk++) {
            float4 a4  = *(const float4*)&As[kk][ty << 2];
            float4 a4b = *(const float4*)&As[kk][(ty << 2) + 64];
            float4 b4  = *(const float4*)&Bs[kk][tx << 2];
            float4 b4b = *(const float4*)&Bs[kk][(tx << 2) + 64];
            float ar[8] = {a4.x, a4.y, a4.z, a4.w, a4b.x, a4b.y, a4b.z, a4b.w};
            float br[8] = {b4.x, b4.y, b4.z, b4.w, b4b.x, b4b.y, b4b.z, b4b.w};
#pragma unroll
            for (int i = 0; i < 8; i++)
#pragma unroll
                for (int j = 0; j < 8; j++)
                    acc[i][j] = fmaf(ar[i], br[j], acc[i][j]);
        }
    }
#pragma unroll
    for (int i = 0; i < 8; i++) {
        int r = m0 + ((i < 4) ? ((ty << 2) + i) : (64 + (ty << 2) + i - 4));
        float2 s0 = split_tf32(acc[i][0]), s1 = split_tf32(acc[i][1]);
        float2 s2 = split_tf32(acc[i][2]), s3 = split_tf32(acc[i][3]);
        float2 s4 = split_tf32(acc[i][4]), s5 = split_tf32(acc[i][5]);
        float2 s6 = split_tf32(acc[i][6]), s7 = split_tf32(acc[i][7]);
        float2* d0 = g_t2 + (size_t)r * Hsz + n0 + (tx << 2);
        *(float4*)(d0)     = make_float4(s0.x, s0.y, s1.x, s1.y);
        *(float4*)(d0 + 2) = make_float4(s2.x, s2.y, s3.x, s3.y);
        float2* d1 = d0 + 64;
        *(float4*)(d1)     = make_float4(s4.x, s4.y, s5.x, s5.y);
        *(float4*)(d1 + 2) = make_float4(s6.x, s6.y, s7.x, s7.y);
    }
}

// ---------------------------------------------------------------------------
// Fused cross-GEMM + argmin via 3xTF32 mma.sync (split precision).
// grid = (4 C-groups, 128 M-tiles). CTA tile 128x128, 8 warps (4m x 2n),
// warp tile 32x64 = 2 m-tiles x 8 n-tiles of m16n8k8.
// smem holds (hi,lo) float2 pairs: As2 [m][k] (pad 22), Bs2 [k][n] (pad 132).
// ---------------------------------------------------------------------------
#define KW 22
#define NW 132

__global__ void __launch_bounds__(256, 2) dist_kernel() {
    const int m0 = blockIdx.y * 128;
    const int grp = blockIdx.x;
    __shared__ __align__(16) float2 As2[128][KW];   // 22.5 KB
    __shared__ __align__(16) float2 Bs2[16][NW];    // 16.9 KB

    const int tid = threadIdx.x;
    const int lane = tid & 31;
    const int wid = tid >> 5;
    const int wm = wid >> 1;        // 0..3 : m offset 32*wm
    const int wn = wid & 1;         // 0..1 : n offset 64*wn
    const int lr = lane >> 2;       // 0..7
    const int lc = lane & 3;        // 0..3

    const int lrow = tid >> 2;      // A loader rows lrow, lrow+64
    const int lk = (tid & 3) << 2;  // k offset 0,4,8,12
    const int brow = wid;           // B loader k-rows brow, brow+8
    const int bcol = lane << 2;     // n offset 0..124

    float bestd[4];
    int besti[4];
#pragma unroll
    for (int s = 0; s < 4; s++) { bestd[s] = FLT_MAX; besti[s] = 0; }

    const float2* Ap0 = g_t2 + (size_t)(m0 + lrow) * Hsz + lk;
    const float2* Ap1 = Ap0 + (size_t)64 * Hsz;

    for (int ct = 0; ct < 16; ct++) {
        const int n0 = (grp << 11) + (ct << 7);
        float acc[2][8][4];
#pragma unroll
        for (int mt = 0; mt < 2; mt++)
#pragma unroll
            for (int nt = 0; nt < 8; nt++)
#pragma unroll
                for (int c = 0; c < 4; c++) acc[mt][nt][c] = 0.f;

        for (int k0 = 0; k0 < Hsz; k0 += 16) {
            float4 u0 = *(const float4*)(Ap0 + k0);
            float4 u1 = *(const float4*)(Ap0 + k0 + 2);
            float4 u2 = *(const float4*)(Ap1 + k0);
            float4 u3 = *(const float4*)(Ap1 + k0 + 2);
            const float2* Bb = g_cb2 + (size_t)(k0 + brow) * Csz + n0 + bcol;
            float4 v0 = *(const float4*)(Bb);
            float4 v1 = *(const float4*)(Bb + 2);
            const float2* Bb2 = Bb + (size_t)8 * Csz;
            float4 v2 = *(const float4*)(Bb2);
            float4 v3 = *(const float4*)(Bb2 + 2);
            __syncthreads();
            *(float4*)&As2[lrow][lk]          = u0;
            *(float4*)&As2[lrow][lk + 2]      = u1;
            *(float4*)&As2[lrow + 64][lk]     = u2;
            *(float4*)&As2[lrow + 64][lk + 2] = u3;
            *(float4*)&Bs2[brow][bcol]         = v0;
            *(float4*)&Bs2[brow][bcol + 2]     = v1;
            *(float4*)&Bs2[brow + 8][bcol]     = v2;
            *(float4*)&Bs2[brow + 8][bcol + 2] = v3;
            __syncthreads();
#pragma unroll
            for (int kb = 0; kb < 16; kb += 8) {
                unsigned ahi[2][4], alo[2][4];
#pragma unroll
                for (int mt = 0; mt < 2; mt++) {
                    const int mb = wm * 32 + mt * 16;
                    float2 a0 = As2[mb + lr][kb + lc];
                    float2 a1 = As2[mb + lr + 8][kb + lc];
                    float2 a2 = As2[mb + lr][kb + lc + 4];
                    float2 a3 = As2[mb + lr + 8][kb + lc + 4];
                    ahi[mt][0] = __float_as_uint(a0.x);
                    ahi[mt][1] = __float_as_uint(a1.x);
                    ahi[mt][2] = __float_as_uint(a2.x);
                    ahi[mt][3] = __float_as_uint(a3.x);
                    alo[mt][0] = __float_as_uint(a0.y);
                    alo[mt][1] = __float_as_uint(a1.y);
                    alo[mt][2] = __float_as_uint(a2.y);
                    alo[mt][3] = __float_as_uint(a3.y);
                }
#pragma unroll
                for (int nt = 0; nt < 8; nt++) {
                    const int nb = wn * 64 + nt * 8;
                    float2 b0 = Bs2[kb + lc][nb + lr];
                    float2 b1 = Bs2[kb + lc + 4][nb + lr];
                    unsigned bh0 = __float_as_uint(b0.x), bh1 = __float_as_uint(b1.x);
                    unsigned bl0 = __float_as_uint(b0.y), bl1 = __float_as_uint(b1.y);
#pragma unroll
                    for (int mt = 0; mt < 2; mt++) {
                        mma_tf32(acc[mt][nt], ahi[mt], bh0, bh1);
                        mma_tf32(acc[mt][nt], ahi[mt], bl0, bl1);
                        mma_tf32(acc[mt][nt], alo[mt], bh0, bh1);
                    }
                }
            }
        }
        // Epilogue: d = csq - 2*cross (argmin-equivalent). Slots:
        // s = mt*2 + (c>=2): row = wm*32 + mt*16 + lr + 8*(s&1).
        // Cols ascend (c0 before c1, nt ascending, ct ascending) -> lowest-index ties.
#pragma unroll
        for (int mt = 0; mt < 2; mt++)
#pragma unroll
            for (int nt = 0; nt < 8; nt++) {
                const int colb = n0 + wn * 64 + nt * 8 + (lc << 1);
                float cs0 = g_csq[colb];
                float cs1 = g_csq[colb + 1];
                float d0 = fmaf(-2.f, acc[mt][nt][0], cs0);
                float d1 = fmaf(-2.f, acc[mt][nt][1], cs1);
                float d2 = fmaf(-2.f, acc[mt][nt][2], cs0);
                float d3 = fmaf(-2.f, acc[mt][nt][3], cs1);
                const int s0 = mt * 2, s1 = mt * 2 + 1;
                if (d0 < bestd[s0]) { bestd[s0] = d0; besti[s0] = colb; }
                if (d1 < bestd[s0]) { bestd[s0] = d1; besti[s0] = colb + 1; }
                if (d2 < bestd[s1]) { bestd[s1] = d2; besti[s1] = colb; }
                if (d3 < bestd[s1]) { bestd[s1] = d3; besti[s1] = colb + 1; }
            }
    }

    // Reduce over the 4 lanes (lc) sharing each row; then over the 2 n-warps.
    __syncthreads();
    float* rd = (float*)&Bs2[0][0];          // 128*2 floats
    int*   ri = (int*)(rd + 256);            // 128*2 ints
#pragma unroll
    for (int s = 0; s < 4; s++) {
        float bd = bestd[s];
        int bi = besti[s];
#pragma unroll
        for (int off = 1; off < 4; off <<= 1) {
            float od = __shfl_xor_sync(0xffffffffu, bd, off);
            int oi = __shfl_xor_sync(0xffffffffu, bi, off);
            if (od < bd || (od == bd && oi < bi)) { bd = od; bi = oi; }
        }
        if (lc == 0) {
            int row = wm * 32 + (s >> 1) * 16 + (s & 1) * 8 + lr;
            rd[row * 2 + wn] = bd;
            ri[row * 2 + wn] = bi;
        }
    }
    __syncthreads();
    if (tid < 128) {
        float d0 = rd[tid * 2], d1 = rd[tid * 2 + 1];
        int i0 = ri[tid * 2], i1 = ri[tid * 2 + 1];
        if (d1 < d0 || (d1 == d0 && i1 < i0)) { d0 = d1; i0 = i1; }
        g_cand_d[grp * Msz + m0 + tid] = d0;
        g_cand_i[grp * Msz + m0 + tid] = i0;
    }
}

// ---------------------------------------------------------------------------
// Merge the 4 per-group candidates per row (ties -> lowest index).
// Labels written AS FLOAT32 (harness output dtype).
// ---------------------------------------------------------------------------
__global__ void __launch_bounds__(256) argmin_final(float* __restrict__ out) {
    const int r = blockIdx.x * blockDim.x + threadIdx.x;
    float bd = g_cand_d[r];
    int bi = g_cand_i[r];
#pragma unroll
    for (int g = 1; g < 4; g++) {
        float d = g_cand_d[g * Msz + r];
        int ii = g_cand_i[g * Msz + r];
        if (d < bd || (d == bd && ii < bi)) { bd = d; bi = ii; }
    }
    out[r] = (float)bi;
}

// ---------------------------------------------------------------------------
// Robust input binding (unit- and order-proof), fallback = dict order.
// ---------------------------------------------------------------------------
extern "C" void kernel_launch(void* const* d_in, const int* in_sizes, int n_in,
                              void* d_out, int out_size) {
    int div = 1;
    {
        bool e1 = false, e4 = false;
        for (int i = 0; i < n_in; i++) {
            if (in_sizes[i] == 524288)  e1 = true;   // proj in elements
            if (in_sizes[i] == 2097152) e4 = true;   // proj in bytes
        }
        if (!e1 && e4) div = 4;
    }
    int iproj = -1, i512a = -1, i512b = -1, ibig1 = -1, ibig2 = -1;
    long long S[16];
    for (int i = 0; i < n_in && i < 16; i++) {
        S[i] = (long long)in_sizes[i] / div;
        if (S[i] == 524288) { if (iproj < 0) iproj = i; }
        else if (S[i] == 512) { if (i512a < 0) i512a = i; else if (i512b < 0) i512b = i; }
        else if (S[i] == 8388608) { if (ibig1 < 0) ibig1 = i; else if (ibig2 < 0) ibig2 = i; }
    }

    const float *x, *pa, *pb, *W, *CB;
    if (iproj >= 0 && i512a >= 0 && i512b >= 0 && ibig1 >= 0 && ibig2 >= 0) {
        int ix, icb;
        if      (ibig1 + 1 < n_in && S[ibig1 + 1] == 512) { ix = ibig1; icb = ibig2; }
        else if (ibig2 + 1 < n_in && S[ibig2 + 1] == 512) { ix = ibig2; icb = ibig1; }
        else if (ibig1 - 1 >= 0   && S[ibig1 - 1] == 512) { ix = ibig1; icb = ibig2; }
        else if (ibig2 - 1 >= 0   && S[ibig2 - 1] == 512) { ix = ibig2; icb = ibig1; }
        else                                              { ix = ibig1; icb = ibig2; }
        x  = (const float*)d_in[ix];
        pa = (const float*)d_in[i512a];
        pb = (const float*)d_in[i512b];
        W  = (const float*)d_in[iproj];
        CB = (const float*)d_in[icb];
    } else {
        x  = (const float*)d_in[0];
        pa = (const float*)d_in[1];
        pb = (const float*)d_in[2];
        W  = (const float*)d_in[3];
        CB = (const float*)d_in[4];
    }
    float* out = (float*)d_out;                  // labels as float32

    ln_kernel<<<Msz, 128>>>(x, pa, pb);
    csq_kernel<<<Csz / 256, 256>>>(CB);
    cb2_kernel<<<(Hsz * Csz) / 256, 256>>>(CB);
    gemm1_kernel<<<dim3(Hsz / 128, Msz / 128), 256>>>(W);
    dist_kernel<<<dim3(4, Msz / 128), 256>>>();
    argmin_final<<<Msz / 256, 256>>>(out);
}

// round 14
// speedup vs baseline: 1.2322x; 1.2322x over previous
#include <cuda_runtime.h>
#include <math.h>
#include <float.h>
#include <stdint.h>

// Problem sizes (fixed by the reference)
#define Msz 16384   // B*L = 8*2048
#define Dsz 512
#define Hsz 1024
#define Csz 8192
#define LN_EPS 1e-5f

// Scratch (static device globals — the sanctioned allocation-free route)
__device__ __align__(16) float g_xn[(size_t)Msz * Dsz];   // 32 MB LayerNorm out
__device__ __align__(16) float g_t[(size_t)Msz * Hsz];    // 64 MB projection out
__device__ __align__(16) float g_csq[Csz];
__device__ __align__(16) float g_cand_d[4 * Msz];
__device__ __align__(16) int   g_cand_i[4 * Msz];

// ---------------------------------------------------------------------------
// LayerNorm: one block (128 threads) per row of 512 floats.
// Weight (== ones) vs bias (== zeros) resolved by content.
// ---------------------------------------------------------------------------
__global__ void __launch_bounds__(128) ln_kernel(const float* __restrict__ x,
                                                 const float* __restrict__ pa,
                                                 const float* __restrict__ pb) {
    const bool a_is_w = (fabsf(pa[0] - 1.0f) < 0.0625f) && (fabsf(pa[1] - 1.0f) < 0.0625f);
    const float* w = a_is_w ? pa : pb;
    const float* b = a_is_w ? pb : pa;

    const int row = blockIdx.x;
    const int t = threadIdx.x;
    const float* xr = x + (size_t)row * Dsz;
    float v0 = xr[t], v1 = xr[t + 128], v2 = xr[t + 256], v3 = xr[t + 384];
    float s  = v0 + v1 + v2 + v3;
    float ss = v0 * v0 + v1 * v1 + v2 * v2 + v3 * v3;
#pragma unroll
    for (int o = 16; o > 0; o >>= 1) {
        s  += __shfl_xor_sync(0xffffffffu, s, o);
        ss += __shfl_xor_sync(0xffffffffu, ss, o);
    }
    __shared__ float rs[4], rss[4];
    __shared__ float smean, sinv;
    const int warp = t >> 5;
    if ((t & 31) == 0) { rs[warp] = s; rss[warp] = ss; }
    __syncthreads();
    if (t == 0) {
        float S  = rs[0] + rs[1] + rs[2] + rs[3];
        float SS = rss[0] + rss[1] + rss[2] + rss[3];
        float mean = S / (float)Dsz;
        float var  = SS / (float)Dsz - mean * mean;
        smean = mean;
        sinv  = 1.0f / sqrtf(var + LN_EPS);
    }
    __syncthreads();
    const float mean = smean, inv = sinv;
    float* orow = g_xn + (size_t)row * Dsz;
    orow[t]       = (v0 - mean) * inv * w[t]       + b[t];
    orow[t + 128] = (v1 - mean) * inv * w[t + 128] + b[t + 128];
    orow[t + 256] = (v2 - mean) * inv * w[t + 256] + b[t + 256];
    orow[t + 384] = (v3 - mean) * inv * w[t + 384] + b[t + 384];
}

// ---------------------------------------------------------------------------
// c_sq[c] = sum_h codebook[h][c]^2   (coalesced column sums)
// ---------------------------------------------------------------------------
__global__ void __launch_bounds__(256) csq_kernel(const float* __restrict__ cb) {
    const int c = blockIdx.x * blockDim.x + threadIdx.x;
    float sum = 0.f;
    for (int h = 0; h < Hsz; h++) {
        float v = cb[(size_t)h * Csz + c];
        sum = fmaf(v, v, sum);
    }
    g_csq[c] = sum;
}

// ---------------------------------------------------------------------------
// GEMM1 (NT): g_t[M,H] = g_xn[M,D] * W[H,D]^T
// 128x128 block tile, BK=16, 256 threads, 8x8 microtile
// ---------------------------------------------------------------------------
__global__ void __launch_bounds__(256) gemm1_kernel(const float* __restrict__ W) {
    const int m0 = blockIdx.y * 128;
    const int n0 = blockIdx.x * 128;
    __shared__ __align__(16) float As[16][132];
    __shared__ __align__(16) float Bs[16][132];
    const int tid = threadIdx.x;
    const int tx = tid & 15;
    const int ty = tid >> 4;
    const int lrow = tid >> 2;          // 0..63
    const int lk = (tid & 3) << 2;      // 0,4,8,12

    float acc[8][8];
#pragma unroll
    for (int i = 0; i < 8; i++)
#pragma unroll
        for (int j = 0; j < 8; j++) acc[i][j] = 0.f;

    const float* Ap = g_xn + (size_t)(m0 + lrow) * Dsz + lk;
    const float* Bp = W + (size_t)(n0 + lrow) * Dsz + lk;

    for (int k0 = 0; k0 < Dsz; k0 += 16) {
        float4 a0 = *(const float4*)(Ap + k0);
        float4 a1 = *(const float4*)(Ap + k0 + (size_t)64 * Dsz);
        float4 b0 = *(const float4*)(Bp + k0);
        float4 b1 = *(const float4*)(Bp + k0 + (size_t)64 * Dsz);
        __syncthreads();
        As[lk + 0][lrow] = a0.x; As[lk + 1][lrow] = a0.y;
        As[lk + 2][lrow] = a0.z; As[lk + 3][lrow] = a0.w;
        As[lk + 0][lrow + 64] = a1.x; As[lk + 1][lrow + 64] = a1.y;
        As[lk + 2][lrow + 64] = a1.z; As[lk + 3][lrow + 64] = a1.w;
        Bs[lk + 0][lrow] = b0.x; Bs[lk + 1][lrow] = b0.y;
        Bs[lk + 2][lrow] = b0.z; Bs[lk + 3][lrow] = b0.w;
        Bs[lk + 0][lrow + 64] = b1.x; Bs[lk + 1][lrow + 64] = b1.y;
        Bs[lk + 2][lrow + 64] = b1.z; Bs[lk + 3][lrow + 64] = b1.w;
        __syncthreads();
#pragma unroll
        for (int kk = 0; kk < 16; kk++) {
            float4 a4  = *(const float4*)&As[kk][ty << 2];
            float4 a4b = *(const float4*)&As[kk][(ty << 2) + 64];
            float4 b4  = *(const float4*)&Bs[kk][tx << 2];
            float4 b4b = *(const float4*)&Bs[kk][(tx << 2) + 64];
            float ar[8] = {a4.x, a4.y, a4.z, a4.w, a4b.x, a4b.y, a4b.z, a4b.w};
            float br[8] = {b4.x, b4.y, b4.z, b4.w, b4b.x, b4b.y, b4b.z, b4b.w};
#pragma unroll
            for (int i = 0; i < 8; i++)
#pragma unroll
                for (int j = 0; j < 8; j++)
                    acc[i][j] = fmaf(ar[i], br[j], acc[i][j]);
        }
    }
#pragma unroll
    for (int i = 0; i < 8; i++) {
        int r = m0 + ((i < 4) ? ((ty << 2) + i) : (64 + (ty << 2) + i - 4));
        float4 o0 = make_float4(acc[i][0], acc[i][1], acc[i][2], acc[i][3]);
        float4 o1 = make_float4(acc[i][4], acc[i][5], acc[i][6], acc[i][7]);
        *(float4*)(g_t + (size_t)r * Hsz + n0 + (tx << 2)) = o0;
        *(float4*)(g_t + (size_t)r * Hsz + n0 + 64 + (tx << 2)) = o1;
    }
}

// ---------------------------------------------------------------------------
// Packed fp32x2 helpers (full-rate fp32; lane ops are IEEE fp32 FMAs, so
// results are bitwise identical to the scalar version).
// ---------------------------------------------------------------------------
__device__ __forceinline__ void ffma2(unsigned long long& d,
                                      unsigned long long a,
                                      unsigned long long b) {
    asm("fma.rn.f32x2 %0, %1, %2, %0;" : "+l"(d) : "l"(a), "l"(b));
}
__device__ __forceinline__ unsigned long long bcast2(float a) {
    unsigned long long r;
    asm("mov.b64 %0, {%1, %1};" : "=l"(r) : "f"(a));
    return r;
}
__device__ __forceinline__ void unpack2(unsigned long long v, float& lo, float& hi) {
    asm("mov.b64 {%0, %1}, %2;" : "=f"(lo), "=f"(hi) : "l"(v));
}
__device__ __forceinline__ void cp_async16(uint32_t dst_smem, const void* src) {
    asm volatile("cp.async.cg.shared.global [%0], [%1], 16;"
                 :: "r"(dst_smem), "l"(src) : "memory");
}

// ---------------------------------------------------------------------------
// Fused cross-GEMM + argmin, 4-way column-group parallel, f32x2 compute,
// software-pipelined double buffering:
//   B tiles stream gmem->smem via cp.async (zero registers, untransposed),
//   A tiles prefetch through 8 registers (transposed smem scatter),
//   ONE barrier per step; 1024 steps = 16 col-tiles x 64 K-steps.
// grid = (4 C-groups, 128 M-tiles) = 512 CTAs, 2 CTAs/SM.
// ---------------------------------------------------------------------------
__global__ void __launch_bounds__(256, 2) dist_kernel(const float* __restrict__ CB) {
    const int m0 = blockIdx.y * 128;
    const int grp = blockIdx.x;
    // 2 buffers x (As 16*132 + Bs 16*132) floats = 8448 floats = 33 KB.
    // sd/si reduction arrays alias this space after the final barrier.
    __shared__ __align__(16) float smem[8448];
    const uint32_t smem_u32 = (uint32_t)__cvta_generic_to_shared(smem);

    const int tid = threadIdx.x;
    const int tx = tid & 15;
    const int ty = tid >> 4;
    const int lrow = tid >> 2;          // A loader: 0..63
    const int lk = (tid & 3) << 2;
    const int brow = tid >> 5;          // B loader: 0..7
    const int bcol = (tid & 31) << 2;   // 0..124

    float bestd[8];
    int besti[8];
#pragma unroll
    for (int i = 0; i < 8; i++) { bestd[i] = FLT_MAX; besti[i] = 0; }

    const float* Ap = g_t + (size_t)(m0 + lrow) * Hsz + lk;

    // Prologue: step 0 (ct=0, k0=0) loaded synchronously into buffer 0.
    {
        float4 a0 = *(const float4*)(Ap);
        float4 a1 = *(const float4*)(Ap + (size_t)64 * Hsz);
        const float* Bb = CB + (size_t)brow * Csz + (grp << 11) + bcol;
        float4 b0 = *(const float4*)(Bb);
        float4 b1 = *(const float4*)(Bb + (size_t)8 * Csz);
        float* As = smem;
        float* Bs = smem + 2112;
        As[(lk + 0) * 132 + lrow] = a0.x; As[(lk + 1) * 132 + lrow] = a0.y;
        As[(lk + 2) * 132 + lrow] = a0.z; As[(lk + 3) * 132 + lrow] = a0.w;
        As[(lk + 0) * 132 + lrow + 64] = a1.x; As[(lk + 1) * 132 + lrow + 64] = a1.y;
        As[(lk + 2) * 132 + lrow + 64] = a1.z; As[(lk + 3) * 132 + lrow + 64] = a1.w;
        *(float4*)&Bs[brow * 132 + bcol] = b0;
        *(float4*)&Bs[(brow + 8) * 132 + bcol] = b1;
    }
    __syncthreads();

    int buf = 0;
    unsigned long long acc2[8][4];
#pragma unroll
    for (int i = 0; i < 8; i++)
#pragma unroll
        for (int p = 0; p < 4; p++) acc2[i][p] = 0ull;

    float4 pa0, pa1;
    for (int s = 0; s < 1024; s++) {
        const bool not_last = (s != 1023);
        // Issue next-step loads: B via cp.async (into buf^1), A into registers.
        if (not_last) {
            const int s1 = s + 1;
            const int k0n = (s1 & 63) << 4;
            const int n0n = (grp << 11) + ((s1 >> 6) << 7);
            const float* Bb = CB + (size_t)(k0n + brow) * Csz + n0n + bcol;
            const uint32_t bdst = smem_u32 +
                ((uint32_t)((buf ^ 1) * 4224 + 2112 + brow * 132 + bcol) << 2);
            cp_async16(bdst, Bb);
            cp_async16(bdst + (8 * 132 << 2), Bb + (size_t)8 * Csz);
            asm volatile("cp.async.commit_group;" ::: "memory");
            pa0 = *(const float4*)(Ap + k0n);
            pa1 = *(const float4*)(Ap + k0n + (size_t)64 * Hsz);
        }
        // Compute current buffer (f32x2; B j-pairs read directly as 64b lanes)
        {
            const float* As = smem + buf * 4224;
            const float* Bs = As + 2112;
#pragma unroll
            for (int kk = 0; kk < 16; kk++) {
                float4 a4  = *(const float4*)&As[kk * 132 + (ty << 2)];
                float4 a4b = *(const float4*)&As[kk * 132 + (ty << 2) + 64];
                ulonglong2 bp0 = *(const ulonglong2*)&Bs[kk * 132 + (tx << 2)];
                ulonglong2 bp1 = *(const ulonglong2*)&Bs[kk * 132 + (tx << 2) + 64];
                unsigned long long b2[4] = {bp0.x, bp0.y, bp1.x, bp1.y};
                unsigned long long a2[8] = {
                    bcast2(a4.x),  bcast2(a4.y),  bcast2(a4.z),  bcast2(a4.w),
                    bcast2(a4b.x), bcast2(a4b.y), bcast2(a4b.z), bcast2(a4b.w)};
#pragma unroll
                for (int i = 0; i < 8; i++)
#pragma unroll
                    for (int p = 0; p < 4; p++)
                        ffma2(acc2[i][p], a2[i], b2[p]);
            }
        }
        // Store A prefetch, drain cp.async, one barrier per step.
        if (not_last) {
            float* As = smem + (buf ^ 1) * 4224;
            As[(lk + 0) * 132 + lrow] = pa0.x; As[(lk + 1) * 132 + lrow] = pa0.y;
            As[(lk + 2) * 132 + lrow] = pa0.z; As[(lk + 3) * 132 + lrow] = pa0.w;
            As[(lk + 0) * 132 + lrow + 64] = pa1.x; As[(lk + 1) * 132 + lrow + 64] = pa1.y;
            As[(lk + 2) * 132 + lrow + 64] = pa1.z; As[(lk + 3) * 132 + lrow + 64] = pa1.w;
            asm volatile("cp.async.wait_group 0;" ::: "memory");
            __syncthreads();
            buf ^= 1;
        }
        // End of a column-tile: fold acc2 into the running argmin, reset.
        if ((s & 63) == 63) {
            const int n0 = (grp << 11) + ((s >> 6) << 7);
#pragma unroll
            for (int p = 0; p < 4; p++) {
                const int base = n0 + ((p < 2) ? (tx << 2) + (p << 1)
                                               : 64 + (tx << 2) + ((p - 2) << 1));
                float cs0 = g_csq[base];
                float cs1 = g_csq[base + 1];
#pragma unroll
                for (int i = 0; i < 8; i++) {
                    float clo, chi;
                    unpack2(acc2[i][p], clo, chi);
                    float d0 = fmaf(-2.0f, clo, cs0);
                    float d1 = fmaf(-2.0f, chi, cs1);
                    if (d0 < bestd[i]) { bestd[i] = d0; besti[i] = base; }
                    if (d1 < bestd[i]) { bestd[i] = d1; besti[i] = base + 1; }
                    acc2[i][p] = 0ull;
                }
            }
        }
    }

    // Cross-thread per-row reduction (16 tx lanes per row), lowest index on tie.
    // sd/si alias the pipeline buffers — barrier first.
    __syncthreads();
    float* sd = smem;                    // 128*17 floats
    int*   si = (int*)(smem + 2176);     // 128*17 ints
#pragma unroll
    for (int i = 0; i < 8; i++) {
        int r = (i < 4) ? ((ty << 2) + i) : (64 + (ty << 2) + i - 4);
        sd[r * 17 + tx] = bestd[i];
        si[r * 17 + tx] = besti[i];
    }
    __syncthreads();
    if (tid < 128) {
        float bd = sd[tid * 17];
        int bi = si[tid * 17];
#pragma unroll
        for (int x = 1; x < 16; x++) {
            float d = sd[tid * 17 + x];
            int ii = si[tid * 17 + x];
            if (d < bd || (d == bd && ii < bi)) { bd = d; bi = ii; }
        }
        g_cand_d[grp * Msz + m0 + tid] = bd;
        g_cand_i[grp * Msz + m0 + tid] = bi;
    }
}

// ---------------------------------------------------------------------------
// Merge the 4 per-group candidates per row (ties -> lowest index).
// Labels written AS FLOAT32 (harness output dtype).
// ---------------------------------------------------------------------------
__global__ void __launch_bounds__(256) argmin_final(float* __restrict__ out) {
    const int r = blockIdx.x * blockDim.x + threadIdx.x;
    float bd = g_cand_d[r];
    int bi = g_cand_i[r];
#pragma unroll
    for (int g = 1; g < 4; g++) {
        float d = g_cand_d[g * Msz + r];
        int ii = g_cand_i[g * Msz + r];
        if (d < bd || (d == bd && ii < bi)) { bd = d; bi = ii; }
    }
    out[r] = (float)bi;
}

// ---------------------------------------------------------------------------
// Robust input binding (unit- and order-proof), fallback = dict order.
// ---------------------------------------------------------------------------
extern "C" void kernel_launch(void* const* d_in, const int* in_sizes, int n_in,
                              void* d_out, int out_size) {
    int div = 1;
    {
        bool e1 = false, e4 = false;
        for (int i = 0; i < n_in; i++) {
            if (in_sizes[i] == 524288)  e1 = true;   // proj in elements
            if (in_sizes[i] == 2097152) e4 = true;   // proj in bytes
        }
        if (!e1 && e4) div = 4;
    }
    int iproj = -1, i512a = -1, i512b = -1, ibig1 = -1, ibig2 = -1;
    long long S[16];
    for (int i = 0; i < n_in && i < 16; i++) {
        S[i] = (long long)in_sizes[i] / div;
        if (S[i] == 524288) { if (iproj < 0) iproj = i; }
        else if (S[i] == 512) { if (i512a < 0) i512a = i; else if (i512b < 0) i512b = i; }
        else if (S[i] == 8388608) { if (ibig1 < 0) ibig1 = i; else if (ibig2 < 0) ibig2 = i; }
    }

    const float *x, *pa, *pb, *W, *CB;
    if (iproj >= 0 && i512a >= 0 && i512b >= 0 && ibig1 >= 0 && ibig2 >= 0) {
        int ix, icb;
        if      (ibig1 + 1 < n_in && S[ibig1 + 1] == 512) { ix = ibig1; icb = ibig2; }
        else if (ibig2 + 1 < n_in && S[ibig2 + 1] == 512) { ix = ibig2; icb = ibig1; }
        else if (ibig1 - 1 >= 0   && S[ibig1 - 1] == 512) { ix = ibig1; icb = ibig2; }
        else if (ibig2 - 1 >= 0   && S[ibig2 - 1] == 512) { ix = ibig2; icb = ibig1; }
        else                                              { ix = ibig1; icb = ibig2; }
        x  = (const float*)d_in[ix];
        pa = (const float*)d_in[i512a];
        pb = (const float*)d_in[i512b];
        W  = (const float*)d_in[iproj];
        CB = (const float*)d_in[icb];
    } else {
        x  = (const float*)d_in[0];
        pa = (const float*)d_in[1];
        pb = (const float*)d_in[2];
        W  = (const float*)d_in[3];
        CB = (const float*)d_in[4];
    }
    float* out = (float*)d_out;                  // labels as float32

    ln_kernel<<<Msz, 128>>>(x, pa, pb);
    csq_kernel<<<Csz / 256, 256>>>(CB);
    gemm1_kernel<<<dim3(Hsz / 128, Msz / 128), 256>>>(W);
    dist_kernel<<<dim3(4, Msz / 128), 256>>>(CB);
    argmin_final<<<Msz / 256, 256>>>(out);
}

// round 15
// speedup vs baseline: 1.4488x; 1.1759x over previous
#include <cuda_runtime.h>
#include <math.h>
#include <float.h>
#include <stdint.h>

// Problem sizes (fixed by the reference)
#define Msz 16384   // B*L = 8*2048
#define Dsz 512
#define Hsz 1024
#define Csz 8192
#define LN_EPS 1e-5f
#define NGRP 16     // codebook column groups (512 cols each) for wave balance

// Scratch (static device globals — the sanctioned allocation-free route)
__device__ __align__(16) float g_xn[(size_t)Msz * Dsz];   // 32 MB LayerNorm out
__device__ __align__(16) float g_t[(size_t)Msz * Hsz];    // 64 MB projection out
__device__ __align__(16) float g_csq[Csz];
__device__ __align__(16) float g_cand_d[NGRP * Msz];
__device__ __align__(16) int   g_cand_i[NGRP * Msz];

// ---------------------------------------------------------------------------
// Packed fp32x2 helpers (full-rate fp32; lane ops are IEEE fp32 FMAs, so
// results are bitwise identical to the scalar version).
// ---------------------------------------------------------------------------
__device__ __forceinline__ void ffma2(unsigned long long& d,
                                      unsigned long long a,
                                      unsigned long long b) {
    asm("fma.rn.f32x2 %0, %1, %2, %0;" : "+l"(d) : "l"(a), "l"(b));
}
__device__ __forceinline__ unsigned long long bcast2(float a) {
    unsigned long long r;
    asm("mov.b64 %0, {%1, %1};" : "=l"(r) : "f"(a));
    return r;
}
__device__ __forceinline__ void unpack2(unsigned long long v, float& lo, float& hi) {
    asm("mov.b64 {%0, %1}, %2;" : "=f"(lo), "=f"(hi) : "l"(v));
}

// ---------------------------------------------------------------------------
// LayerNorm: one block (128 threads) per row of 512 floats.
// Weight (== ones) vs bias (== zeros) resolved by content.
// ---------------------------------------------------------------------------
__global__ void __launch_bounds__(128) ln_kernel(const float* __restrict__ x,
                                                 const float* __restrict__ pa,
                                                 const float* __restrict__ pb) {
    const bool a_is_w = (fabsf(pa[0] - 1.0f) < 0.0625f) && (fabsf(pa[1] - 1.0f) < 0.0625f);
    const float* w = a_is_w ? pa : pb;
    const float* b = a_is_w ? pb : pa;

    const int row = blockIdx.x;
    const int t = threadIdx.x;
    const float* xr = x + (size_t)row * Dsz;
    float v0 = xr[t], v1 = xr[t + 128], v2 = xr[t + 256], v3 = xr[t + 384];
    float s  = v0 + v1 + v2 + v3;
    float ss = v0 * v0 + v1 * v1 + v2 * v2 + v3 * v3;
#pragma unroll
    for (int o = 16; o > 0; o >>= 1) {
        s  += __shfl_xor_sync(0xffffffffu, s, o);
        ss += __shfl_xor_sync(0xffffffffu, ss, o);
    }
    __shared__ float rs[4], rss[4];
    __shared__ float smean, sinv;
    const int warp = t >> 5;
    if ((t & 31) == 0) { rs[warp] = s; rss[warp] = ss; }
    __syncthreads();
    if (t == 0) {
        float S  = rs[0] + rs[1] + rs[2] + rs[3];
        float SS = rss[0] + rss[1] + rss[2] + rss[3];
        float mean = S / (float)Dsz;
        float var  = SS / (float)Dsz - mean * mean;
        smean = mean;
        sinv  = 1.0f / sqrtf(var + LN_EPS);
    }
    __syncthreads();
    const float mean = smean, inv = sinv;
    float* orow = g_xn + (size_t)row * Dsz;
    orow[t]       = (v0 - mean) * inv * w[t]       + b[t];
    orow[t + 128] = (v1 - mean) * inv * w[t + 128] + b[t + 128];
    orow[t + 256] = (v2 - mean) * inv * w[t + 256] + b[t + 256];
    orow[t + 384] = (v3 - mean) * inv * w[t + 384] + b[t + 384];
}

// ---------------------------------------------------------------------------
// c_sq[c] = sum_h codebook[h][c]^2   (coalesced column sums)
// ---------------------------------------------------------------------------
__global__ void __launch_bounds__(256) csq_kernel(const float* __restrict__ cb) {
    const int c = blockIdx.x * blockDim.x + threadIdx.x;
    float sum = 0.f;
    for (int h = 0; h < Hsz; h++) {
        float v = cb[(size_t)h * Csz + c];
        sum = fmaf(v, v, sum);
    }
    g_csq[c] = sum;
}

// ---------------------------------------------------------------------------
// GEMM1 (NT): g_t[M,H] = g_xn[M,D] * W[H,D]^T
// 128x128 block tile, BK=16, 256 threads, 8x8 microtile, f32x2 compute.
// ---------------------------------------------------------------------------
__global__ void __launch_bounds__(256) gemm1_kernel(const float* __restrict__ W) {
    const int m0 = blockIdx.y * 128;
    const int n0 = blockIdx.x * 128;
    __shared__ __align__(16) float As[16][132];
    __shared__ __align__(16) float Bs[16][132];
    const int tid = threadIdx.x;
    const int tx = tid & 15;
    const int ty = tid >> 4;
    const int lrow = tid >> 2;          // 0..63
    const int lk = (tid & 3) << 2;      // 0,4,8,12

    unsigned long long acc2[8][4];
#pragma unroll
    for (int i = 0; i < 8; i++)
#pragma unroll
        for (int p = 0; p < 4; p++) acc2[i][p] = 0ull;

    const float* Ap = g_xn + (size_t)(m0 + lrow) * Dsz + lk;
    const float* Bp = W + (size_t)(n0 + lrow) * Dsz + lk;

    for (int k0 = 0; k0 < Dsz; k0 += 16) {
        float4 a0 = *(const float4*)(Ap + k0);
        float4 a1 = *(const float4*)(Ap + k0 + (size_t)64 * Dsz);
        float4 b0 = *(const float4*)(Bp + k0);
        float4 b1 = *(const float4*)(Bp + k0 + (size_t)64 * Dsz);
        __syncthreads();
        As[lk + 0][lrow] = a0.x; As[lk + 1][lrow] = a0.y;
        As[lk + 2][lrow] = a0.z; As[lk + 3][lrow] = a0.w;
        As[lk + 0][lrow + 64] = a1.x; As[lk + 1][lrow + 64] = a1.y;
        As[lk + 2][lrow + 64] = a1.z; As[lk + 3][lrow + 64] = a1.w;
        Bs[lk + 0][lrow] = b0.x; Bs[lk + 1][lrow] = b0.y;
        Bs[lk + 2][lrow] = b0.z; Bs[lk + 3][lrow] = b0.w;
        Bs[lk + 0][lrow + 64] = b1.x; Bs[lk + 1][lrow + 64] = b1.y;
        Bs[lk + 2][lrow + 64] = b1.z; Bs[lk + 3][lrow + 64] = b1.w;
        __syncthreads();
#pragma unroll
        for (int kk = 0; kk < 16; kk++) {
            float4 a4  = *(const float4*)&As[kk][ty << 2];
            float4 a4b = *(const float4*)&As[kk][(ty << 2) + 64];
            ulonglong2 bp0 = *(const ulonglong2*)&Bs[kk][tx << 2];
            ulonglong2 bp1 = *(const ulonglong2*)&Bs[kk][(tx << 2) + 64];
            unsigned long long b2[4] = {bp0.x, bp0.y, bp1.x, bp1.y};
            unsigned long long a2[8] = {
                bcast2(a4.x),  bcast2(a4.y),  bcast2(a4.z),  bcast2(a4.w),
                bcast2(a4b.x), bcast2(a4b.y), bcast2(a4b.z), bcast2(a4b.w)};
#pragma unroll
            for (int i = 0; i < 8; i++)
#pragma unroll
                for (int p = 0; p < 4; p++)
                    ffma2(acc2[i][p], a2[i], b2[p]);
        }
    }
#pragma unroll
    for (int i = 0; i < 8; i++) {
        int r = m0 + ((i < 4) ? ((ty << 2) + i) : (64 + (ty << 2) + i - 4));
        float c0, c1, c2, c3, c4, c5, c6, c7;
        unpack2(acc2[i][0], c0, c1); unpack2(acc2[i][1], c2, c3);
        unpack2(acc2[i][2], c4, c5); unpack2(acc2[i][3], c6, c7);
        *(float4*)(g_t + (size_t)r * Hsz + n0 + (tx << 2)) = make_float4(c0, c1, c2, c3);
        *(float4*)(g_t + (size_t)r * Hsz + n0 + 64 + (tx << 2)) = make_float4(c4, c5, c6, c7);
    }
}

// ---------------------------------------------------------------------------
// Fused cross-GEMM + argmin, 16-way column-group parallel, f32x2 compute.
// grid = (16 C-groups x 512 cols, 128 M-tiles) = 2048 CTAs at 2 CTAs/SM
// -> 6.92 waves -> 98.8% slot utilization (vs 86.5% at 512 CTAs).
// Inner loop identical to the proven R10 kernel.
// ---------------------------------------------------------------------------
__global__ void __launch_bounds__(256, 2) dist_kernel(const float* __restrict__ CB) {
    const int m0 = blockIdx.y * 128;
    const int grp = blockIdx.x;         // 0..15, 512 columns each
    __shared__ __align__(16) float As[16][132];
    __shared__ __align__(16) float Bs[16][132];
    __shared__ float sd[128][17];
    __shared__ int   si[128][17];

    const int tid = threadIdx.x;
    const int tx = tid & 15;
    const int ty = tid >> 4;
    const int lrow = tid >> 2;          // A loader: 0..63
    const int lk = (tid & 3) << 2;
    const int brow = tid >> 5;          // B loader: 0..7
    const int bcol = (tid & 31) << 2;   // 0..124

    float bestd[8];
    int besti[8];
#pragma unroll
    for (int i = 0; i < 8; i++) { bestd[i] = FLT_MAX; besti[i] = 0; }

    const float* Ap = g_t + (size_t)(m0 + lrow) * Hsz + lk;

    for (int ct = 0; ct < 4; ct++) {
        const int n0 = (grp << 9) + (ct << 7);
        unsigned long long acc2[8][4];
#pragma unroll
        for (int i = 0; i < 8; i++)
#pragma unroll
            for (int p = 0; p < 4; p++) acc2[i][p] = 0ull;

        for (int k0 = 0; k0 < Hsz; k0 += 16) {
            float4 a0 = *(const float4*)(Ap + k0);
            float4 a1 = *(const float4*)(Ap + k0 + (size_t)64 * Hsz);
            const float* Bbase = CB + (size_t)(k0 + brow) * Csz + n0 + bcol;
            float4 b0 = *(const float4*)(Bbase);
            float4 b1 = *(const float4*)(Bbase + (size_t)8 * Csz);
            __syncthreads();
            As[lk + 0][lrow] = a0.x; As[lk + 1][lrow] = a0.y;
            As[lk + 2][lrow] = a0.z; As[lk + 3][lrow] = a0.w;
            As[lk + 0][lrow + 64] = a1.x; As[lk + 1][lrow + 64] = a1.y;
            As[lk + 2][lrow + 64] = a1.z; As[lk + 3][lrow + 64] = a1.w;
            Bs[brow][bcol + 0] = b0.x; Bs[brow][bcol + 1] = b0.y;
            Bs[brow][bcol + 2] = b0.z; Bs[brow][bcol + 3] = b0.w;
            Bs[brow + 8][bcol + 0] = b1.x; Bs[brow + 8][bcol + 1] = b1.y;
            Bs[brow + 8][bcol + 2] = b1.z; Bs[brow + 8][bcol + 3] = b1.w;
            __syncthreads();
#pragma unroll
            for (int kk = 0; kk < 16; kk++) {
                float4 a4  = *(const float4*)&As[kk][ty << 2];
                float4 a4b = *(const float4*)&As[kk][(ty << 2) + 64];
                ulonglong2 bp0 = *(const ulonglong2*)&Bs[kk][tx << 2];
                ulonglong2 bp1 = *(const ulonglong2*)&Bs[kk][(tx << 2) + 64];
                unsigned long long b2[4] = {bp0.x, bp0.y, bp1.x, bp1.y};
                unsigned long long a2[8] = {
                    bcast2(a4.x),  bcast2(a4.y),  bcast2(a4.z),  bcast2(a4.w),
                    bcast2(a4b.x), bcast2(a4b.y), bcast2(a4b.z), bcast2(a4b.w)};
#pragma unroll
                for (int i = 0; i < 8; i++)
#pragma unroll
                    for (int p = 0; p < 4; p++)
                        ffma2(acc2[i][p], a2[i], b2[p]);
            }
        }
        // Epilogue: score = csq - 2*cross (argmin-equivalent to d2),
        // columns strictly ascending within the group -> lowest-index ties.
#pragma unroll
        for (int p = 0; p < 4; p++) {
            const int base = n0 + ((p < 2) ? (tx << 2) + (p << 1)
                                           : 64 + (tx << 2) + ((p - 2) << 1));
            float cs0 = g_csq[base];
            float cs1 = g_csq[base + 1];
#pragma unroll
            for (int i = 0; i < 8; i++) {
                float clo, chi;
                unpack2(acc2[i][p], clo, chi);
                float d0 = fmaf(-2.0f, clo, cs0);
                float d1 = fmaf(-2.0f, chi, cs1);
                if (d0 < bestd[i]) { bestd[i] = d0; besti[i] = base; }
                if (d1 < bestd[i]) { bestd[i] = d1; besti[i] = base + 1; }
            }
        }
    }

    // Cross-thread per-row reduction (16 tx lanes per row), lowest index on tie
    __syncthreads();
#pragma unroll
    for (int i = 0; i < 8; i++) {
        int r = (i < 4) ? ((ty << 2) + i) : (64 + (ty << 2) + i - 4);
        sd[r][tx] = bestd[i];
        si[r][tx] = besti[i];
    }
    __syncthreads();
    if (tid < 128) {
        float bd = sd[tid][0];
        int bi = si[tid][0];
#pragma unroll
        for (int x = 1; x < 16; x++) {
            float d = sd[tid][x];
            int ii = si[tid][x];
            if (d < bd || (d == bd && ii < bi)) { bd = d; bi = ii; }
        }
        g_cand_d[grp * Msz + m0 + tid] = bd;
        g_cand_i[grp * Msz + m0 + tid] = bi;
    }
}

// ---------------------------------------------------------------------------
// Merge the 16 per-group candidates per row (ties -> lowest index).
// Labels written AS FLOAT32 (harness output dtype).
// ---------------------------------------------------------------------------
__global__ void __launch_bounds__(256) argmin_final(float* __restrict__ out) {
    const int r = blockIdx.x * blockDim.x + threadIdx.x;
    float bd = g_cand_d[r];
    int bi = g_cand_i[r];
#pragma unroll
    for (int g = 1; g < NGRP; g++) {
        float d = g_cand_d[g * Msz + r];
        int ii = g_cand_i[g * Msz + r];
        if (d < bd || (d == bd && ii < bi)) { bd = d; bi = ii; }
    }
    out[r] = (float)bi;
}

// ---------------------------------------------------------------------------
// Robust input binding (unit- and order-proof), fallback = dict order.
// ---------------------------------------------------------------------------
extern "C" void kernel_launch(void* const* d_in, const int* in_sizes, int n_in,
                              void* d_out, int out_size) {
    int div = 1;
    {
        bool e1 = false, e4 = false;
        for (int i = 0; i < n_in; i++) {
            if (in_sizes[i] == 524288)  e1 = true;   // proj in elements
            if (in_sizes[i] == 2097152) e4 = true;   // proj in bytes
        }
        if (!e1 && e4) div = 4;
    }
    int iproj = -1, i512a = -1, i512b = -1, ibig1 = -1, ibig2 = -1;
    long long S[16];
    for (int i = 0; i < n_in && i < 16; i++) {
        S[i] = (long long)in_sizes[i] / div;
        if (S[i] == 524288) { if (iproj < 0) iproj = i; }
        else if (S[i] == 512) { if (i512a < 0) i512a = i; else if (i512b < 0) i512b = i; }
        else if (S[i] == 8388608) { if (ibig1 < 0) ibig1 = i; else if (ibig2 < 0) ibig2 = i; }
    }

    const float *x, *pa, *pb, *W, *CB;
    if (iproj >= 0 && i512a >= 0 && i512b >= 0 && ibig1 >= 0 && ibig2 >= 0) {
        int ix, icb;
        if      (ibig1 + 1 < n_in && S[ibig1 + 1] == 512) { ix = ibig1; icb = ibig2; }
        else if (ibig2 + 1 < n_in && S[ibig2 + 1] == 512) { ix = ibig2; icb = ibig1; }
        else if (ibig1 - 1 >= 0   && S[ibig1 - 1] == 512) { ix = ibig1; icb = ibig2; }
        else if (ibig2 - 1 >= 0   && S[ibig2 - 1] == 512) { ix = ibig2; icb = ibig1; }
        else                                              { ix = ibig1; icb = ibig2; }
        x  = (const float*)d_in[ix];
        pa = (const float*)d_in[i512a];
        pb = (const float*)d_in[i512b];
        W  = (const float*)d_in[iproj];
        CB = (const float*)d_in[icb];
    } else {
        x  = (const float*)d_in[0];
        pa = (const float*)d_in[1];
        pb = (const float*)d_in[2];
        W  = (const float*)d_in[3];
        CB = (const float*)d_in[4];
    }
    float* out = (float*)d_out;                  // labels as float32

    ln_kernel<<<Msz, 128>>>(x, pa, pb);
    csq_kernel<<<Csz / 256, 256>>>(CB);
    gemm1_kernel<<<dim3(Hsz / 128, Msz / 128), 256>>>(W);
    dist_kernel<<<dim3(NGRP, Msz / 128), 256>>>(CB);
    argmin_final<<<Msz / 256, 256>>>(out);
}